// round 13
// baseline (speedup 1.0000x reference)
#include <cuda_runtime.h>
#include <cuda_bf16.h>
#include <cstdint>
#include <cstddef>

#define HWSZ 40000
#define CD   128

// ---- scratch (static device globals; no runtime allocation) ----
// NOTE: only referenced from device code (host-side kernel args of __device__
// symbols give host-shadow addresses — the round-7/8 bug).
__device__ float g_kv[4UL * 256 * 40000];        // conv output [n][o][pos] fp32
__device__ float g_tmp[2UL * 40000 * 128];       // q after head 0 (channels-last fp32)
__device__ __align__(16) __nv_bfloat16 g_xhi[4UL * 40000 * 128];   // X split-bf16
__device__ __align__(16) __nv_bfloat16 g_xlo[4UL * 40000 * 128];
__device__ __align__(16) __nv_bfloat16 g_whi[256 * 128];           // conv weight split
__device__ __align__(16) __nv_bfloat16 g_wlo[256 * 128];
__device__ __align__(16) __nv_bfloat16 g_pwhi[128 * 128];          // proj weight split
__device__ __align__(16) __nv_bfloat16 g_pwlo[128 * 128];
__device__ __align__(16) __nv_bfloat16 g_q2hi[2UL * 40000 * 128];  // q after head 1, split
__device__ __align__(16) __nv_bfloat16 g_q2lo[2UL * 40000 * 128];

// ===========================================================================
// PTX helpers
// ===========================================================================
__device__ __forceinline__ uint32_t smem_u32(const void* p) {
    uint32_t a;
    asm("{ .reg .u64 t; cvta.to.shared.u64 t, %1; cvt.u32.u64 %0, t; }"
        : "=r"(a) : "l"(p));
    return a;
}
#define LDMX4(r, addr)                                                        \
    asm volatile("ldmatrix.sync.aligned.m8n8.x4.shared.b16 {%0,%1,%2,%3}, [%4];" \
                 : "=r"((r)[0]), "=r"((r)[1]), "=r"((r)[2]), "=r"((r)[3])     \
                 : "r"(addr))
__device__ __forceinline__ void mma16816(float* d, const uint32_t* a,
                                         uint32_t b0, uint32_t b1) {
    asm volatile(
        "mma.sync.aligned.m16n8k16.row.col.f32.bf16.bf16.f32 "
        "{%0,%1,%2,%3}, {%4,%5,%6,%7}, {%8,%9}, {%0,%1,%2,%3};"
        : "+f"(d[0]), "+f"(d[1]), "+f"(d[2]), "+f"(d[3])
        : "r"(a[0]), "r"(a[1]), "r"(a[2]), "r"(a[3]), "r"(b0), "r"(b1));
}
#define CPA16(dst, src) \
    asm volatile("cp.async.cg.shared.global [%0], [%1], 16;" :: "r"(dst), "l"(src) : "memory")
#define CPA16Z(dst, src, sz) \
    asm volatile("cp.async.cg.shared.global [%0], [%1], 16, %2;" :: "r"(dst), "l"(src), "r"(sz) : "memory")
#define CPA_COMMIT() asm volatile("cp.async.commit_group;" ::: "memory")
#define CPA_WAIT1()  asm volatile("cp.async.wait_group 1;" ::: "memory")
#define CPA_WAIT0()  asm volatile("cp.async.wait_group 0;" ::: "memory")

// ===========================================================================
// split-bf16 conversion pre-pass. Destinations bound IN DEVICE CODE.
// ===========================================================================
__device__ __forceinline__ void split4(float4 v, uint2& hw, uint2& lw) {
    float f[4] = {v.x, v.y, v.z, v.w};
    uint32_t h2[2] = {0, 0}, l2[2] = {0, 0};
#pragma unroll
    for (int k = 0; k < 4; k++) {
        __nv_bfloat16 h = __float2bfloat16(f[k]);
        __nv_bfloat16 l = __float2bfloat16(f[k] - __bfloat162float(h));
        h2[k >> 1] |= (uint32_t)__bfloat16_as_ushort(h) << ((k & 1) * 16);
        l2[k >> 1] |= (uint32_t)__bfloat16_as_ushort(l) << ((k & 1) * 16);
    }
    hw = make_uint2(h2[0], h2[1]);
    lw = make_uint2(l2[0], l2[1]);
}

__global__ void __launch_bounds__(256) cvt_x_kernel(const float* __restrict__ x) {
    int i = blockIdx.x * blockDim.x + threadIdx.x;   // over 5,120,000 float4
    if (i >= 5120000) return;
    uint2 hw, lw;
    split4(((const float4*)x)[i], hw, lw);
    ((uint2*)g_xhi)[i] = hw;
    ((uint2*)g_xlo)[i] = lw;
}

__global__ void __launch_bounds__(256) cvt_w_kernel(const float* __restrict__ kvw,
                                                    const float* __restrict__ pw) {
    int i = blockIdx.x * blockDim.x + threadIdx.x;   // 8192 kvw + 4096 pw float4
    uint2 hw, lw;
    if (i < 8192) {
        split4(((const float4*)kvw)[i], hw, lw);
        ((uint2*)g_whi)[i] = hw;
        ((uint2*)g_wlo)[i] = lw;
    } else if (i < 12288) {
        int j = i - 8192;
        split4(((const float4*)pw)[j], hw, lw);
        ((uint2*)g_pwhi)[j] = hw;
        ((uint2*)g_pwlo)[j] = lw;
    }
}

// ===========================================================================
// GEMM tile layout: 128 rows x 128 bf16 cols, padded rows of 272B (136 elems).
// 272 mod 128 = 16 -> consecutive rows shift 4 banks: ldmatrix conflict-free.
// ===========================================================================
#define RSB  272                     // row stride bytes
#define TLB  (128 * RSB)             // one tile = 34816B
#define A_HI 0
#define A_LO (TLB)
#define B_HI (2 * TLB)
#define B_LO (3 * TLB)
#define SMT  (4 * TLB)               // 139264B dynamic smem

// one split-bf16 pass: acc += A(ab) * B(bb)^T over full K=128
__device__ __forceinline__ void gemm_pass(uint32_t ab, uint32_t bb, int lane,
                                          int wm, int wn, float acc[4][4][4]) {
    const int arow  = wm + (lane & 15);
    const int acolb = ((lane >> 4) << 3);
    const int brow  = wn + (lane & 7) + ((lane >> 4) << 3);
    const int bcolb = (((lane >> 3) & 1) << 3);
#pragma unroll
    for (int ks = 0; ks < 8; ks++) {
        uint32_t a[4][4], b[2][4];
        int kc = ks * 16;
#pragma unroll
        for (int mt = 0; mt < 4; mt++)
            LDMX4(a[mt], ab + (uint32_t)(arow + mt * 16) * RSB
                           + (uint32_t)(kc + acolb) * 2);
#pragma unroll
        for (int np = 0; np < 2; np++)
            LDMX4(b[np], bb + (uint32_t)(brow + np * 16) * RSB
                           + (uint32_t)(kc + bcolb) * 2);
#pragma unroll
        for (int mt = 0; mt < 4; mt++)
#pragma unroll
            for (int nt = 0; nt < 4; nt++)
                mma16816(acc[mt][nt], a[mt],
                         b[nt >> 1][(nt & 1) * 2], b[nt >> 1][(nt & 1) * 2 + 1]);
    }
}

// ---------------------------------------------------------------------------
// conv 1x1: g_kv[n][o][p] = sum_c W[o][c] * X[n][p][c]
// grid (313 p-tiles, 2 o-blocks of 128, 4 n), 256 threads (8 warps: 2m x 4n).
// Split-commit: HI tiles (group 1) -> pass HI x HI overlaps LO tile loads.
// ---------------------------------------------------------------------------
__global__ void __launch_bounds__(256, 1) conv_hmma_kernel() {
    extern __shared__ char sm[];
    uint32_t sb = smem_u32(sm);
    const int tid = threadIdx.x, wid = tid >> 5, lane = tid & 31;
    const int p0 = blockIdx.x * 128;
    const int o0 = blockIdx.y * 128;
    const int n  = blockIdx.z;
    const size_t xoff = (size_t)n * HWSZ * CD;

    // ---- group 1: A_HI + B_HI ----
#pragma unroll
    for (int i = 0; i < 8; i++) {                    // A_HI: 2048 segs
        int idx = tid + i * 256;
        int c16 = idx & 15, row = idx >> 4;
        CPA16(sb + A_HI + (uint32_t)row * RSB + (uint32_t)c16 * 16,
              g_whi + (size_t)(o0 + row) * CD + c16 * 8);
    }
#pragma unroll
    for (int i = 0; i < 8; i++) {                    // B_HI
        int idx = tid + i * 256;
        int c16 = idx & 15, row = idx >> 4;
        int p = p0 + row;
        int sz = (p < HWSZ) ? 16 : 0;
        int pc = (p < HWSZ) ? p : 0;
        CPA16Z(sb + B_HI + (uint32_t)row * RSB + (uint32_t)c16 * 16,
               g_xhi + xoff + (size_t)pc * CD + c16 * 8, sz);
    }
    CPA_COMMIT();
    // ---- group 2: A_LO + B_LO ----
#pragma unroll
    for (int i = 0; i < 8; i++) {
        int idx = tid + i * 256;
        int c16 = idx & 15, row = idx >> 4;
        CPA16(sb + A_LO + (uint32_t)row * RSB + (uint32_t)c16 * 16,
              g_wlo + (size_t)(o0 + row) * CD + c16 * 8);
    }
#pragma unroll
    for (int i = 0; i < 8; i++) {
        int idx = tid + i * 256;
        int c16 = idx & 15, row = idx >> 4;
        int p = p0 + row;
        int sz = (p < HWSZ) ? 16 : 0;
        int pc = (p < HWSZ) ? p : 0;
        CPA16Z(sb + B_LO + (uint32_t)row * RSB + (uint32_t)c16 * 16,
               g_xlo + xoff + (size_t)pc * CD + c16 * 8, sz);
    }
    CPA_COMMIT();

    const int wm = (wid & 1) * 64, wn = (wid >> 1) * 32;
    float acc[4][4][4];
#pragma unroll
    for (int i = 0; i < 4; i++)
#pragma unroll
        for (int j = 0; j < 4; j++)
#pragma unroll
            for (int k = 0; k < 4; k++) acc[i][j][k] = 0.f;

    CPA_WAIT1();
    __syncthreads();
    gemm_pass(sb + A_HI, sb + B_HI, lane, wm, wn, acc);   // overlaps LO loads
    CPA_WAIT0();
    __syncthreads();
    gemm_pass(sb + A_LO, sb + B_HI, lane, wm, wn, acc);
    gemm_pass(sb + A_HI, sb + B_LO, lane, wm, wn, acc);

    const int g = lane >> 2, tg = lane & 3;
    float* O = g_kv + (size_t)n * 256 * HWSZ;
#pragma unroll
    for (int mt = 0; mt < 4; mt++) {
        int rr = o0 + wm + mt * 16 + g;
#pragma unroll
        for (int nt = 0; nt < 4; nt++) {
            int pp = p0 + wn + nt * 8 + tg * 2;
            if (pp < HWSZ) {
                *(float2*)&O[(size_t)rr * HWSZ + pp] =
                    make_float2(acc[mt][nt][0], acc[mt][nt][1]);
                *(float2*)&O[(size_t)(rr + 8) * HWSZ + pp] =
                    make_float2(acc[mt][nt][2], acc[mt][nt][3]);
            }
        }
    }
}

// ---------------------------------------------------------------------------
// projection: out[p][co] = sum_c q2[p][c] * Wp[co][c] + bias[co]
// grid (625 p-tiles of 128 over 80000), 256 threads. Same split-commit.
// ---------------------------------------------------------------------------
__global__ void __launch_bounds__(256, 1)
proj_hmma_kernel(const float* __restrict__ bias, float* __restrict__ out) {
    extern __shared__ char sm[];
    uint32_t sb = smem_u32(sm);
    const int tid = threadIdx.x, wid = tid >> 5, lane = tid & 31;
    const int p0 = blockIdx.x * 128;

    // group 1: A_HI (q2hi) + B_HI (pwhi)
#pragma unroll
    for (int i = 0; i < 8; i++) {
        int idx = tid + i * 256;
        int c16 = idx & 15, row = idx >> 4;
        CPA16(sb + A_HI + (uint32_t)row * RSB + (uint32_t)c16 * 16,
              g_q2hi + (size_t)(p0 + row) * CD + c16 * 8);
    }
#pragma unroll
    for (int i = 0; i < 8; i++) {
        int idx = tid + i * 256;
        int c16 = idx & 15, row = idx >> 4;
        CPA16(sb + B_HI + (uint32_t)row * RSB + (uint32_t)c16 * 16,
              g_pwhi + (size_t)row * CD + c16 * 8);
    }
    CPA_COMMIT();
    // group 2: A_LO + B_LO
#pragma unroll
    for (int i = 0; i < 8; i++) {
        int idx = tid + i * 256;
        int c16 = idx & 15, row = idx >> 4;
        CPA16(sb + A_LO + (uint32_t)row * RSB + (uint32_t)c16 * 16,
              g_q2lo + (size_t)(p0 + row) * CD + c16 * 8);
    }
#pragma unroll
    for (int i = 0; i < 8; i++) {
        int idx = tid + i * 256;
        int c16 = idx & 15, row = idx >> 4;
        CPA16(sb + B_LO + (uint32_t)row * RSB + (uint32_t)c16 * 16,
              g_pwlo + (size_t)row * CD + c16 * 8);
    }
    CPA_COMMIT();

    const int wm = (wid & 1) * 64, wn = (wid >> 1) * 32;
    float acc[4][4][4];
#pragma unroll
    for (int i = 0; i < 4; i++)
#pragma unroll
        for (int j = 0; j < 4; j++)
#pragma unroll
            for (int k = 0; k < 4; k++) acc[i][j][k] = 0.f;

    CPA_WAIT1();
    __syncthreads();
    gemm_pass(sb + A_HI, sb + B_HI, lane, wm, wn, acc);
    CPA_WAIT0();
    __syncthreads();
    gemm_pass(sb + A_LO, sb + B_HI, lane, wm, wn, acc);
    gemm_pass(sb + A_HI, sb + B_LO, lane, wm, wn, acc);

    const int g = lane >> 2, tg = lane & 3;
#pragma unroll
    for (int mt = 0; mt < 4; mt++) {
        int p = p0 + wm + mt * 16 + g;
#pragma unroll
        for (int nt = 0; nt < 4; nt++) {
            int co = wn + nt * 8 + tg * 2;
            float b0 = bias[co], b1 = bias[co + 1];
            *(float2*)&out[(size_t)p * CD + co] =
                make_float2(acc[mt][nt][0] + b0, acc[mt][nt][1] + b1);
            *(float2*)&out[(size_t)(p + 8) * CD + co] =
                make_float2(acc[mt][nt][2] + b0, acc[mt][nt][3] + b1);
        }
    }
}

// ---------------------------------------------------------------------------
// Dilate attention, 4-way channel-packed, COMPRESSED tables (42KB smem ->
// 5 blocks/SM = 20 warps). One tab read + one mask feeds 4 gathers at
// offsets {0, +640000, +1280000, +1920000} (stream identities, round 12).
// ---------------------------------------------------------------------------
__global__ void __launch_bounds__(128, 5) attn_kernel(const float* __restrict__ qext,
                                                      int head, int dil, int stage) {
    __shared__ int           tabx[1800];   // 7.2KB: (m/9)*25600 + di*128 + dj
    __shared__ unsigned char tabd[1800];   // 1.8KB: (di+2) | ((dj+2)<<4)
    __shared__ float st[64 * 129];         // 33KB
    const int tid = threadIdx.x;

    for (int m = tid; m < 1800; m += 128) {
        int c200 = m / 9;
        int kk = m - c200 * 9;
        int i = kk / 3;
        int j = kk - i * 3;
        int di = (i - 1) * dil;
        int dj = (j - 1) * dil;
        tabx[m] = c200 * 25600 + di * 128 + dj;
        tabd[m] = (unsigned char)((di + 2) | ((dj + 2) << 4));
    }
    __syncthreads();

    const float* qin = stage ? g_tmp : qext;

    const int b    = blockIdx.y;
    const int pl   = tid & 63;
    const int nh2  = tid >> 6;          // 64-channel slab: 0 or 1
    const int pos0 = blockIdx.x * 64;
    const int pos  = pos0 + pl;         // always < 40000 (625*64 == 40000)
    const int cb   = nh2 * 64;

    const float* Qf = qin + (size_t)b * HWSZ * CD;
    const float* Kb = g_kv + ((size_t)(2 * b) * 256 + head * 128) * HWSZ;
    const float* Vb = g_kv + ((size_t)(2 * b + 1) * 256 + head * 128) * HWSZ;

    const int G0 = nh2 * 576 * 40000 + pos;
    const int m0 = G0 / 25600;
    const int l0 = G0 - m0 * 25600;

    // ---- pass 1: scores for both softmax groups in the slab ----
    float sc0[9], sc1[9];
#pragma unroll
    for (int k = 0; k < 9; k++) { sc0[k] = 0.f; sc1[k] = 0.f; }

    int M = m0, L = l0;
#pragma unroll 1
    for (int hd = 0; hd < 16; hd++) {
        float q0 = Qf[(size_t)(cb + hd) * HWSZ + pos];
        float q1 = Qf[(size_t)(cb + hd + 16) * HWSZ + pos];
        float q2 = Qf[(size_t)(cb + hd + 32) * HWSZ + pos];
        float q3 = Qf[(size_t)(cb + hd + 48) * HWSZ + pos];
#pragma unroll
        for (int kk = 0; kk < 9; kk++) {
            int ax = tabx[M];
            int d  = tabd[M];
            int di = (d & 15) - 2;
            int dj = (d >> 4) - 2;
            int lw = L >> 7, lc = L & 127;
            bool ok = ((unsigned)(lw + di) < 200u) && ((unsigned)(lc + dj) < 128u);
            int a = ax + L;
            float k0 = ok ? __ldg(&Kb[a])           : 0.f;
            float k1 = ok ? __ldg(&Kb[a + 640000])  : 0.f;
            float k2 = ok ? __ldg(&Kb[a + 1280000]) : 0.f;
            float k3 = ok ? __ldg(&Kb[a + 1920000]) : 0.f;
            sc0[kk] = fmaf(q0, k0, sc0[kk]);
            sc0[kk] = fmaf(q1, k1, sc0[kk]);
            sc1[kk] = fmaf(q2, k2, sc1[kk]);
            sc1[kk] = fmaf(q3, k3, sc1[kk]);
            M += 1; L += 14400;
            if (L >= 25600) { L -= 25600; M += 1; }
        }
    }

    // ---- softmax over 9, per group ----
    const float SCALE = 0.17677669529663687f;   // 32^-0.5
    {
        float mx0 = -1e30f, mx1 = -1e30f;
#pragma unroll
        for (int k = 0; k < 9; k++) {
            sc0[k] *= SCALE; mx0 = fmaxf(mx0, sc0[k]);
            sc1[k] *= SCALE; mx1 = fmaxf(mx1, sc1[k]);
        }
        float s0 = 0.f, s1 = 0.f;
#pragma unroll
        for (int k = 0; k < 9; k++) {
            sc0[k] = __expf(sc0[k] - mx0); s0 += sc0[k];
            sc1[k] = __expf(sc1[k] - mx1); s1 += sc1[k];
        }
        float i0 = 1.0f / s0, i1 = 1.0f / s1;
#pragma unroll
        for (int k = 0; k < 9; k++) { sc0[k] *= i0; sc1[k] *= i1; }
    }

    // ---- pass 2: outputs ----
    M = m0; L = l0;
#pragma unroll 1
    for (int hd = 0; hd < 16; hd++) {
        float o0 = 0.f, o1 = 0.f, o2 = 0.f, o3 = 0.f;
#pragma unroll
        for (int kk = 0; kk < 9; kk++) {
            int ax = tabx[M];
            int d  = tabd[M];
            int di = (d & 15) - 2;
            int dj = (d >> 4) - 2;
            int lw = L >> 7, lc = L & 127;
            bool ok = ((unsigned)(lw + di) < 200u) && ((unsigned)(lc + dj) < 128u);
            int a = ax + L;
            float v0 = ok ? __ldg(&Vb[a])           : 0.f;
            float v1 = ok ? __ldg(&Vb[a + 640000])  : 0.f;
            float v2 = ok ? __ldg(&Vb[a + 1280000]) : 0.f;
            float v3 = ok ? __ldg(&Vb[a + 1920000]) : 0.f;
            o0 = fmaf(sc0[kk], v0, o0);
            o1 = fmaf(sc0[kk], v1, o1);
            o2 = fmaf(sc1[kk], v2, o2);
            o3 = fmaf(sc1[kk], v3, o3);
            M += 1; L += 14400;
            if (L >= 25600) { L -= 25600; M += 1; }
        }
        st[pl * 129 + cb + hd]      = o0;
        st[pl * 129 + cb + hd + 16] = o1;
        st[pl * 129 + cb + hd + 32] = o2;
        st[pl * 129 + cb + hd + 48] = o3;
    }
    __syncthreads();

    // coalesced channels-last writeback: 64 pos x 128 ch contiguous
    const size_t obase = (size_t)b * HWSZ * CD + (size_t)pos0 * CD;
    if (stage) {
        __nv_bfloat16* Hh = g_q2hi + obase;
        __nv_bfloat16* Hl = g_q2lo + obase;
#pragma unroll
        for (int it = 0; it < 64; it++) {
            int f = tid + it * 128;
            int p = f >> 7, c = f & 127;
            float v = st[p * 129 + c];
            __nv_bfloat16 h = __float2bfloat16(v);
            Hh[f] = h;
            Hl[f] = __float2bfloat16(v - __bfloat162float(h));
        }
    } else {
        float* Ob = g_tmp + obase;
#pragma unroll
        for (int it = 0; it < 64; it++) {
            int f = tid + it * 128;
            int p = f >> 7, c = f & 127;
            Ob[f] = st[p * 129 + c];
        }
    }
}

extern "C" void kernel_launch(void* const* d_in, const int* in_sizes, int n_in,
                              void* d_out, int out_size) {
    const float* q   = (const float*)d_in[0];
    const float* x   = (const float*)d_in[1];
    const float* kvw = (const float*)d_in[2];
    const float* pw  = (const float*)d_in[3];
    const float* pb  = (const float*)d_in[4];
    float* out = (float*)d_out;

    cudaFuncSetAttribute(conv_hmma_kernel, cudaFuncAttributeMaxDynamicSharedMemorySize, SMT);
    cudaFuncSetAttribute(proj_hmma_kernel, cudaFuncAttributeMaxDynamicSharedMemorySize, SMT);

    cvt_x_kernel<<<20000, 256>>>(x);
    cvt_w_kernel<<<48, 256>>>(kvw, pw);

    conv_hmma_kernel<<<dim3(313, 2, 4), 256, SMT>>>();
    attn_kernel<<<dim3(625, 2), 128>>>(q, /*head=*/0, /*dil=*/1, /*stage=*/0);
    attn_kernel<<<dim3(625, 2), 128>>>(q, /*head=*/1, /*dil=*/2, /*stage=*/1);
    proj_hmma_kernel<<<625, 256, SMT>>>(pb, out);
}

// round 14
// speedup vs baseline: 1.1015x; 1.1015x over previous
#include <cuda_runtime.h>
#include <cuda_bf16.h>
#include <cstdint>
#include <cstddef>

#define HWSZ 40000
#define CD   128

// ---- scratch (static device globals; no runtime allocation) ----
// NOTE: only referenced from device code (host-side kernel args of __device__
// symbols give host-shadow addresses — the round-7/8 bug).
__device__ float g_kv[4UL * 256 * 40000];        // conv output [n][o][pos] fp32
__device__ float g_tmp[2UL * 40000 * 128];       // q after head 0 (channels-last fp32)
__device__ __align__(16) __nv_bfloat16 g_xhi[4UL * 40000 * 128];   // X split-bf16
__device__ __align__(16) __nv_bfloat16 g_xlo[4UL * 40000 * 128];
__device__ __align__(16) __nv_bfloat16 g_whi[256 * 128];           // conv weight split
__device__ __align__(16) __nv_bfloat16 g_wlo[256 * 128];
__device__ __align__(16) __nv_bfloat16 g_pwhi[128 * 128];          // proj weight split
__device__ __align__(16) __nv_bfloat16 g_pwlo[128 * 128];
__device__ __align__(16) __nv_bfloat16 g_q2hi[2UL * 40000 * 128];  // q after head 1, split
__device__ __align__(16) __nv_bfloat16 g_q2lo[2UL * 40000 * 128];

// ===========================================================================
// PTX helpers
// ===========================================================================
__device__ __forceinline__ uint32_t smem_u32(const void* p) {
    uint32_t a;
    asm("{ .reg .u64 t; cvta.to.shared.u64 t, %1; cvt.u32.u64 %0, t; }"
        : "=r"(a) : "l"(p));
    return a;
}
#define LDMX4(r, addr)                                                        \
    asm volatile("ldmatrix.sync.aligned.m8n8.x4.shared.b16 {%0,%1,%2,%3}, [%4];" \
                 : "=r"((r)[0]), "=r"((r)[1]), "=r"((r)[2]), "=r"((r)[3])     \
                 : "r"(addr))
__device__ __forceinline__ void mma16816(float* d, const uint32_t* a,
                                         uint32_t b0, uint32_t b1) {
    asm volatile(
        "mma.sync.aligned.m16n8k16.row.col.f32.bf16.bf16.f32 "
        "{%0,%1,%2,%3}, {%4,%5,%6,%7}, {%8,%9}, {%0,%1,%2,%3};"
        : "+f"(d[0]), "+f"(d[1]), "+f"(d[2]), "+f"(d[3])
        : "r"(a[0]), "r"(a[1]), "r"(a[2]), "r"(a[3]), "r"(b0), "r"(b1));
}
#define CPA16(dst, src) \
    asm volatile("cp.async.cg.shared.global [%0], [%1], 16;" :: "r"(dst), "l"(src) : "memory")
#define CPA16Z(dst, src, sz) \
    asm volatile("cp.async.cg.shared.global [%0], [%1], 16, %2;" :: "r"(dst), "l"(src), "r"(sz) : "memory")
#define CPA_COMMIT() asm volatile("cp.async.commit_group;" ::: "memory")
#define CPA_WAIT1()  asm volatile("cp.async.wait_group 1;" ::: "memory")
#define CPA_WAIT0()  asm volatile("cp.async.wait_group 0;" ::: "memory")

// ===========================================================================
// split-bf16 conversion pre-pass. Destinations bound IN DEVICE CODE.
// ===========================================================================
__device__ __forceinline__ void split4(float4 v, uint2& hw, uint2& lw) {
    float f[4] = {v.x, v.y, v.z, v.w};
    uint32_t h2[2] = {0, 0}, l2[2] = {0, 0};
#pragma unroll
    for (int k = 0; k < 4; k++) {
        __nv_bfloat16 h = __float2bfloat16(f[k]);
        __nv_bfloat16 l = __float2bfloat16(f[k] - __bfloat162float(h));
        h2[k >> 1] |= (uint32_t)__bfloat16_as_ushort(h) << ((k & 1) * 16);
        l2[k >> 1] |= (uint32_t)__bfloat16_as_ushort(l) << ((k & 1) * 16);
    }
    hw = make_uint2(h2[0], h2[1]);
    lw = make_uint2(l2[0], l2[1]);
}

__global__ void __launch_bounds__(256) cvt_x_kernel(const float* __restrict__ x) {
    int i = blockIdx.x * blockDim.x + threadIdx.x;   // over 5,120,000 float4
    if (i >= 5120000) return;
    uint2 hw, lw;
    split4(((const float4*)x)[i], hw, lw);
    ((uint2*)g_xhi)[i] = hw;
    ((uint2*)g_xlo)[i] = lw;
}

__global__ void __launch_bounds__(256) cvt_w_kernel(const float* __restrict__ kvw,
                                                    const float* __restrict__ pw) {
    int i = blockIdx.x * blockDim.x + threadIdx.x;   // 8192 kvw + 4096 pw float4
    uint2 hw, lw;
    if (i < 8192) {
        split4(((const float4*)kvw)[i], hw, lw);
        ((uint2*)g_whi)[i] = hw;
        ((uint2*)g_wlo)[i] = lw;
    } else if (i < 12288) {
        int j = i - 8192;
        split4(((const float4*)pw)[j], hw, lw);
        ((uint2*)g_pwhi)[j] = hw;
        ((uint2*)g_pwlo)[j] = lw;
    }
}

// ===========================================================================
// GEMM tile layout: 128 rows x 128 bf16 cols, padded rows of 272B (136 elems).
// 272 mod 128 = 16 -> consecutive rows shift 4 banks: ldmatrix conflict-free.
// ===========================================================================
#define RSB  272                     // row stride bytes
#define TLB  (128 * RSB)             // one tile = 34816B
#define A_HI 0
#define A_LO (TLB)
#define B_HI (2 * TLB)
#define B_LO (3 * TLB)
#define SMT  (4 * TLB)               // 139264B dynamic smem

// one split-bf16 pass: acc += A(ab) * B(bb)^T over full K=128
__device__ __forceinline__ void gemm_pass(uint32_t ab, uint32_t bb, int lane,
                                          int wm, int wn, float acc[4][4][4]) {
    const int arow  = wm + (lane & 15);
    const int acolb = ((lane >> 4) << 3);
    const int brow  = wn + (lane & 7) + ((lane >> 4) << 3);
    const int bcolb = (((lane >> 3) & 1) << 3);
#pragma unroll
    for (int ks = 0; ks < 8; ks++) {
        uint32_t a[4][4], b[2][4];
        int kc = ks * 16;
#pragma unroll
        for (int mt = 0; mt < 4; mt++)
            LDMX4(a[mt], ab + (uint32_t)(arow + mt * 16) * RSB
                           + (uint32_t)(kc + acolb) * 2);
#pragma unroll
        for (int np = 0; np < 2; np++)
            LDMX4(b[np], bb + (uint32_t)(brow + np * 16) * RSB
                           + (uint32_t)(kc + bcolb) * 2);
#pragma unroll
        for (int mt = 0; mt < 4; mt++)
#pragma unroll
            for (int nt = 0; nt < 4; nt++)
                mma16816(acc[mt][nt], a[mt],
                         b[nt >> 1][(nt & 1) * 2], b[nt >> 1][(nt & 1) * 2 + 1]);
    }
}

// ---------------------------------------------------------------------------
// conv 1x1: g_kv[n][o][p] = sum_c W[o][c] * X[n][p][c]
// grid (313 p-tiles, 2 o-blocks of 128, 4 n), 256 threads (8 warps: 2m x 4n).
// Split-commit: HI tiles (group 1) -> pass HI x HI overlaps LO tile loads.
// ---------------------------------------------------------------------------
__global__ void __launch_bounds__(256, 1) conv_hmma_kernel() {
    extern __shared__ char sm[];
    uint32_t sb = smem_u32(sm);
    const int tid = threadIdx.x, wid = tid >> 5, lane = tid & 31;
    const int p0 = blockIdx.x * 128;
    const int o0 = blockIdx.y * 128;
    const int n  = blockIdx.z;
    const size_t xoff = (size_t)n * HWSZ * CD;

    // ---- group 1: A_HI + B_HI ----
#pragma unroll
    for (int i = 0; i < 8; i++) {                    // A_HI: 2048 segs
        int idx = tid + i * 256;
        int c16 = idx & 15, row = idx >> 4;
        CPA16(sb + A_HI + (uint32_t)row * RSB + (uint32_t)c16 * 16,
              g_whi + (size_t)(o0 + row) * CD + c16 * 8);
    }
#pragma unroll
    for (int i = 0; i < 8; i++) {                    // B_HI
        int idx = tid + i * 256;
        int c16 = idx & 15, row = idx >> 4;
        int p = p0 + row;
        int sz = (p < HWSZ) ? 16 : 0;
        int pc = (p < HWSZ) ? p : 0;
        CPA16Z(sb + B_HI + (uint32_t)row * RSB + (uint32_t)c16 * 16,
               g_xhi + xoff + (size_t)pc * CD + c16 * 8, sz);
    }
    CPA_COMMIT();
    // ---- group 2: A_LO + B_LO ----
#pragma unroll
    for (int i = 0; i < 8; i++) {
        int idx = tid + i * 256;
        int c16 = idx & 15, row = idx >> 4;
        CPA16(sb + A_LO + (uint32_t)row * RSB + (uint32_t)c16 * 16,
              g_wlo + (size_t)(o0 + row) * CD + c16 * 8);
    }
#pragma unroll
    for (int i = 0; i < 8; i++) {
        int idx = tid + i * 256;
        int c16 = idx & 15, row = idx >> 4;
        int p = p0 + row;
        int sz = (p < HWSZ) ? 16 : 0;
        int pc = (p < HWSZ) ? p : 0;
        CPA16Z(sb + B_LO + (uint32_t)row * RSB + (uint32_t)c16 * 16,
               g_xlo + xoff + (size_t)pc * CD + c16 * 8, sz);
    }
    CPA_COMMIT();

    const int wm = (wid & 1) * 64, wn = (wid >> 1) * 32;
    float acc[4][4][4];
#pragma unroll
    for (int i = 0; i < 4; i++)
#pragma unroll
        for (int j = 0; j < 4; j++)
#pragma unroll
            for (int k = 0; k < 4; k++) acc[i][j][k] = 0.f;

    CPA_WAIT1();
    __syncthreads();
    gemm_pass(sb + A_HI, sb + B_HI, lane, wm, wn, acc);   // overlaps LO loads
    CPA_WAIT0();
    __syncthreads();
    gemm_pass(sb + A_LO, sb + B_HI, lane, wm, wn, acc);
    gemm_pass(sb + A_HI, sb + B_LO, lane, wm, wn, acc);

    const int g = lane >> 2, tg = lane & 3;
    float* O = g_kv + (size_t)n * 256 * HWSZ;
#pragma unroll
    for (int mt = 0; mt < 4; mt++) {
        int rr = o0 + wm + mt * 16 + g;
#pragma unroll
        for (int nt = 0; nt < 4; nt++) {
            int pp = p0 + wn + nt * 8 + tg * 2;
            if (pp < HWSZ) {
                *(float2*)&O[(size_t)rr * HWSZ + pp] =
                    make_float2(acc[mt][nt][0], acc[mt][nt][1]);
                *(float2*)&O[(size_t)(rr + 8) * HWSZ + pp] =
                    make_float2(acc[mt][nt][2], acc[mt][nt][3]);
            }
        }
    }
}

// ---------------------------------------------------------------------------
// projection: out[p][co] = sum_c q2[p][c] * Wp[co][c] + bias[co]
// grid (625 p-tiles of 128 over 80000), 256 threads. Same split-commit.
// ---------------------------------------------------------------------------
__global__ void __launch_bounds__(256, 1)
proj_hmma_kernel(const float* __restrict__ bias, float* __restrict__ out) {
    extern __shared__ char sm[];
    uint32_t sb = smem_u32(sm);
    const int tid = threadIdx.x, wid = tid >> 5, lane = tid & 31;
    const int p0 = blockIdx.x * 128;

    // group 1: A_HI (q2hi) + B_HI (pwhi)
#pragma unroll
    for (int i = 0; i < 8; i++) {
        int idx = tid + i * 256;
        int c16 = idx & 15, row = idx >> 4;
        CPA16(sb + A_HI + (uint32_t)row * RSB + (uint32_t)c16 * 16,
              g_q2hi + (size_t)(p0 + row) * CD + c16 * 8);
    }
#pragma unroll
    for (int i = 0; i < 8; i++) {
        int idx = tid + i * 256;
        int c16 = idx & 15, row = idx >> 4;
        CPA16(sb + B_HI + (uint32_t)row * RSB + (uint32_t)c16 * 16,
              g_pwhi + (size_t)row * CD + c16 * 8);
    }
    CPA_COMMIT();
    // group 2: A_LO + B_LO
#pragma unroll
    for (int i = 0; i < 8; i++) {
        int idx = tid + i * 256;
        int c16 = idx & 15, row = idx >> 4;
        CPA16(sb + A_LO + (uint32_t)row * RSB + (uint32_t)c16 * 16,
              g_q2lo + (size_t)(p0 + row) * CD + c16 * 8);
    }
#pragma unroll
    for (int i = 0; i < 8; i++) {
        int idx = tid + i * 256;
        int c16 = idx & 15, row = idx >> 4;
        CPA16(sb + B_LO + (uint32_t)row * RSB + (uint32_t)c16 * 16,
              g_pwlo + (size_t)row * CD + c16 * 8);
    }
    CPA_COMMIT();

    const int wm = (wid & 1) * 64, wn = (wid >> 1) * 32;
    float acc[4][4][4];
#pragma unroll
    for (int i = 0; i < 4; i++)
#pragma unroll
        for (int j = 0; j < 4; j++)
#pragma unroll
            for (int k = 0; k < 4; k++) acc[i][j][k] = 0.f;

    CPA_WAIT1();
    __syncthreads();
    gemm_pass(sb + A_HI, sb + B_HI, lane, wm, wn, acc);
    CPA_WAIT0();
    __syncthreads();
    gemm_pass(sb + A_LO, sb + B_HI, lane, wm, wn, acc);
    gemm_pass(sb + A_HI, sb + B_LO, lane, wm, wn, acc);

    const int g = lane >> 2, tg = lane & 3;
#pragma unroll
    for (int mt = 0; mt < 4; mt++) {
        int p = p0 + wm + mt * 16 + g;
#pragma unroll
        for (int nt = 0; nt < 4; nt++) {
            int co = wn + nt * 8 + tg * 2;
            float b0 = bias[co], b1 = bias[co + 1];
            *(float2*)&out[(size_t)p * CD + co] =
                make_float2(acc[mt][nt][0] + b0, acc[mt][nt][1] + b1);
            *(float2*)&out[(size_t)(p + 8) * CD + co] =
                make_float2(acc[mt][nt][2] + b0, acc[mt][nt][3] + b1);
        }
    }
}

// ---------------------------------------------------------------------------
// Dilate attention, 4-way channel-packed (round-12 proven version).
// Stream identities: step offsets +144/+288/+432 leave (L, mask, di, dj)
// unchanged, shifting tab index by +225/+450/+675; tab[M+225k] ==
// { tab[M].x + k*640000, tab[M].y }. One tab read + one mask feeds 4 gathers.
// Thread = (pos, 64-channel slab). Block 128 thr = 64 pos x 2 slabs.
// head 1 writes its output directly as split-bf16 for the projection GEMM.
// ---------------------------------------------------------------------------
__global__ void __launch_bounds__(128, 4) attn_kernel(const float* __restrict__ qext,
                                                      int head, int dil, int stage) {
    __shared__ int2  tab[1800];
    __shared__ float st[64 * 129];
    const int tid = threadIdx.x;

    for (int m = tid; m < 1800; m += 128) {
        int c200 = m / 9;
        int kk = m - c200 * 9;
        int i = kk / 3;
        int j = kk - i * 3;
        int di = (i - 1) * dil;
        int dj = (j - 1) * dil;
        tab[m] = make_int2(c200 * 25600 + di * 128 + dj, (di << 16) | (dj & 0xFFFF));
    }
    __syncthreads();

    const float* qin = stage ? g_tmp : qext;

    const int b    = blockIdx.y;
    const int pl   = tid & 63;
    const int nh2  = tid >> 6;          // 64-channel slab: 0 or 1
    const int pos0 = blockIdx.x * 64;
    const int pos  = pos0 + pl;         // always < 40000 (625*64 == 40000)
    const int cb   = nh2 * 64;          // slab channel base

    const float* Qf = qin + (size_t)b * HWSZ * CD;
    const float* Kb = g_kv + ((size_t)(2 * b) * 256 + head * 128) * HWSZ;
    const float* Vb = g_kv + ((size_t)(2 * b + 1) * 256 + head * 128) * HWSZ;

    const int G0 = nh2 * 576 * 40000 + pos;
    const int m0 = G0 / 25600;
    const int l0 = G0 - m0 * 25600;

    // ---- pass 1: scores for both softmax groups in the slab ----
    float sc0[9], sc1[9];
#pragma unroll
    for (int k = 0; k < 9; k++) { sc0[k] = 0.f; sc1[k] = 0.f; }

    int M = m0, L = l0;
#pragma unroll 1
    for (int hd = 0; hd < 16; hd++) {
        float q0 = Qf[(size_t)(cb + hd) * HWSZ + pos];
        float q1 = Qf[(size_t)(cb + hd + 16) * HWSZ + pos];
        float q2 = Qf[(size_t)(cb + hd + 32) * HWSZ + pos];
        float q3 = Qf[(size_t)(cb + hd + 48) * HWSZ + pos];
#pragma unroll
        for (int kk = 0; kk < 9; kk++) {
            int2 t = tab[M];
            int lw = L >> 7, lc = L & 127;
            int di = t.y >> 16;
            int dj = (int)(short)(t.y & 0xFFFF);
            bool ok = ((unsigned)(lw + di) < 200u) && ((unsigned)(lc + dj) < 128u);
            int a = t.x + L;
            float k0 = ok ? __ldg(&Kb[a])           : 0.f;
            float k1 = ok ? __ldg(&Kb[a + 640000])  : 0.f;
            float k2 = ok ? __ldg(&Kb[a + 1280000]) : 0.f;
            float k3 = ok ? __ldg(&Kb[a + 1920000]) : 0.f;
            sc0[kk] = fmaf(q0, k0, sc0[kk]);
            sc0[kk] = fmaf(q1, k1, sc0[kk]);
            sc1[kk] = fmaf(q2, k2, sc1[kk]);
            sc1[kk] = fmaf(q3, k3, sc1[kk]);
            M += 1; L += 14400;
            if (L >= 25600) { L -= 25600; M += 1; }
        }
    }

    // ---- softmax over 9, per group ----
    const float SCALE = 0.17677669529663687f;   // 32^-0.5
    {
        float mx0 = -1e30f, mx1 = -1e30f;
#pragma unroll
        for (int k = 0; k < 9; k++) {
            sc0[k] *= SCALE; mx0 = fmaxf(mx0, sc0[k]);
            sc1[k] *= SCALE; mx1 = fmaxf(mx1, sc1[k]);
        }
        float s0 = 0.f, s1 = 0.f;
#pragma unroll
        for (int k = 0; k < 9; k++) {
            sc0[k] = __expf(sc0[k] - mx0); s0 += sc0[k];
            sc1[k] = __expf(sc1[k] - mx1); s1 += sc1[k];
        }
        float i0 = 1.0f / s0, i1 = 1.0f / s1;
#pragma unroll
        for (int k = 0; k < 9; k++) { sc0[k] *= i0; sc1[k] *= i1; }
    }

    // ---- pass 2: outputs ----
    M = m0; L = l0;
#pragma unroll 1
    for (int hd = 0; hd < 16; hd++) {
        float o0 = 0.f, o1 = 0.f, o2 = 0.f, o3 = 0.f;
#pragma unroll
        for (int kk = 0; kk < 9; kk++) {
            int2 t = tab[M];
            int lw = L >> 7, lc = L & 127;
            int di = t.y >> 16;
            int dj = (int)(short)(t.y & 0xFFFF);
            bool ok = ((unsigned)(lw + di) < 200u) && ((unsigned)(lc + dj) < 128u);
            int a = t.x + L;
            float v0 = ok ? __ldg(&Vb[a])           : 0.f;
            float v1 = ok ? __ldg(&Vb[a + 640000])  : 0.f;
            float v2 = ok ? __ldg(&Vb[a + 1280000]) : 0.f;
            float v3 = ok ? __ldg(&Vb[a + 1920000]) : 0.f;
            o0 = fmaf(sc0[kk], v0, o0);
            o1 = fmaf(sc0[kk], v1, o1);
            o2 = fmaf(sc1[kk], v2, o2);
            o3 = fmaf(sc1[kk], v3, o3);
            M += 1; L += 14400;
            if (L >= 25600) { L -= 25600; M += 1; }
        }
        st[pl * 129 + cb + hd]      = o0;
        st[pl * 129 + cb + hd + 16] = o1;
        st[pl * 129 + cb + hd + 32] = o2;
        st[pl * 129 + cb + hd + 48] = o3;
    }
    __syncthreads();

    // coalesced channels-last writeback: 64 pos x 128 ch contiguous
    const size_t obase = (size_t)b * HWSZ * CD + (size_t)pos0 * CD;
    if (stage) {
        __nv_bfloat16* Hh = g_q2hi + obase;
        __nv_bfloat16* Hl = g_q2lo + obase;
#pragma unroll
        for (int it = 0; it < 64; it++) {
            int f = tid + it * 128;
            int p = f >> 7, c = f & 127;
            float v = st[p * 129 + c];
            __nv_bfloat16 h = __float2bfloat16(v);
            Hh[f] = h;
            Hl[f] = __float2bfloat16(v - __bfloat162float(h));
        }
    } else {
        float* Ob = g_tmp + obase;
#pragma unroll
        for (int it = 0; it < 64; it++) {
            int f = tid + it * 128;
            int p = f >> 7, c = f & 127;
            Ob[f] = st[p * 129 + c];
        }
    }
}

extern "C" void kernel_launch(void* const* d_in, const int* in_sizes, int n_in,
                              void* d_out, int out_size) {
    const float* q   = (const float*)d_in[0];
    const float* x   = (const float*)d_in[1];
    const float* kvw = (const float*)d_in[2];
    const float* pw  = (const float*)d_in[3];
    const float* pb  = (const float*)d_in[4];
    float* out = (float*)d_out;

    cudaFuncSetAttribute(conv_hmma_kernel, cudaFuncAttributeMaxDynamicSharedMemorySize, SMT);
    cudaFuncSetAttribute(proj_hmma_kernel, cudaFuncAttributeMaxDynamicSharedMemorySize, SMT);

    cvt_x_kernel<<<20000, 256>>>(x);
    cvt_w_kernel<<<48, 256>>>(kvw, pw);

    conv_hmma_kernel<<<dim3(313, 2, 4), 256, SMT>>>();
    attn_kernel<<<dim3(625, 2), 128>>>(q, /*head=*/0, /*dil=*/1, /*stage=*/0);
    attn_kernel<<<dim3(625, 2), 128>>>(q, /*head=*/1, /*dil=*/2, /*stage=*/1);
    proj_hmma_kernel<<<625, 256, SMT>>>(pb, out);
}

// round 15
// speedup vs baseline: 1.1313x; 1.0271x over previous
#include <cuda_runtime.h>
#include <cuda_bf16.h>
#include <cstdint>
#include <cstddef>

#define HWSZ 40000
#define CD   128

// ---- scratch (static device globals; no runtime allocation) ----
// NOTE: only referenced from device code (host-side kernel args of __device__
// symbols give host-shadow addresses — the round-7/8 bug).
__device__ float g_kv[4UL * 256 * 40000];        // conv output [n][o][pos] fp32
__device__ float g_tmp[2UL * 40000 * 128];       // q after head 0 (channels-last fp32)
__device__ __align__(16) __nv_bfloat16 g_xhi[4UL * 40000 * 128];   // X split-bf16
__device__ __align__(16) __nv_bfloat16 g_xlo[4UL * 40000 * 128];
__device__ __align__(16) __nv_bfloat16 g_whi[256 * 128];           // conv weight split
__device__ __align__(16) __nv_bfloat16 g_wlo[256 * 128];
__device__ __align__(16) __nv_bfloat16 g_pwhi[128 * 128];          // proj weight split
__device__ __align__(16) __nv_bfloat16 g_pwlo[128 * 128];
__device__ __align__(16) __nv_bfloat16 g_q2hi[2UL * 40000 * 128];  // q after head 1, split
__device__ __align__(16) __nv_bfloat16 g_q2lo[2UL * 40000 * 128];

// ===========================================================================
// PTX helpers
// ===========================================================================
__device__ __forceinline__ uint32_t smem_u32(const void* p) {
    uint32_t a;
    asm("{ .reg .u64 t; cvta.to.shared.u64 t, %1; cvt.u32.u64 %0, t; }"
        : "=r"(a) : "l"(p));
    return a;
}
#define LDMX4(r, addr)                                                        \
    asm volatile("ldmatrix.sync.aligned.m8n8.x4.shared.b16 {%0,%1,%2,%3}, [%4];" \
                 : "=r"((r)[0]), "=r"((r)[1]), "=r"((r)[2]), "=r"((r)[3])     \
                 : "r"(addr))
__device__ __forceinline__ void mma16816(float* d, const uint32_t* a,
                                         uint32_t b0, uint32_t b1) {
    asm volatile(
        "mma.sync.aligned.m16n8k16.row.col.f32.bf16.bf16.f32 "
        "{%0,%1,%2,%3}, {%4,%5,%6,%7}, {%8,%9}, {%0,%1,%2,%3};"
        : "+f"(d[0]), "+f"(d[1]), "+f"(d[2]), "+f"(d[3])
        : "r"(a[0]), "r"(a[1]), "r"(a[2]), "r"(a[3]), "r"(b0), "r"(b1));
}
#define CPA16(dst, src) \
    asm volatile("cp.async.cg.shared.global [%0], [%1], 16;" :: "r"(dst), "l"(src) : "memory")
#define CPA16Z(dst, src, sz) \
    asm volatile("cp.async.cg.shared.global [%0], [%1], 16, %2;" :: "r"(dst), "l"(src), "r"(sz) : "memory")
#define CPA_COMMIT() asm volatile("cp.async.commit_group;" ::: "memory")
#define CPA_WAIT1()  asm volatile("cp.async.wait_group 1;" ::: "memory")
#define CPA_WAIT0()  asm volatile("cp.async.wait_group 0;" ::: "memory")

// ===========================================================================
// split-bf16 conversion pre-pass. Destinations bound IN DEVICE CODE.
// ===========================================================================
__device__ __forceinline__ void split4(float4 v, uint2& hw, uint2& lw) {
    float f[4] = {v.x, v.y, v.z, v.w};
    uint32_t h2[2] = {0, 0}, l2[2] = {0, 0};
#pragma unroll
    for (int k = 0; k < 4; k++) {
        __nv_bfloat16 h = __float2bfloat16(f[k]);
        __nv_bfloat16 l = __float2bfloat16(f[k] - __bfloat162float(h));
        h2[k >> 1] |= (uint32_t)__bfloat16_as_ushort(h) << ((k & 1) * 16);
        l2[k >> 1] |= (uint32_t)__bfloat16_as_ushort(l) << ((k & 1) * 16);
    }
    hw = make_uint2(h2[0], h2[1]);
    lw = make_uint2(l2[0], l2[1]);
}

__global__ void __launch_bounds__(256) cvt_x_kernel(const float* __restrict__ x) {
    int i = blockIdx.x * blockDim.x + threadIdx.x;   // over 5,120,000 float4
    if (i >= 5120000) return;
    uint2 hw, lw;
    split4(((const float4*)x)[i], hw, lw);
    ((uint2*)g_xhi)[i] = hw;
    ((uint2*)g_xlo)[i] = lw;
}

__global__ void __launch_bounds__(256) cvt_w_kernel(const float* __restrict__ kvw,
                                                    const float* __restrict__ pw) {
    int i = blockIdx.x * blockDim.x + threadIdx.x;   // 8192 kvw + 4096 pw float4
    uint2 hw, lw;
    if (i < 8192) {
        split4(((const float4*)kvw)[i], hw, lw);
        ((uint2*)g_whi)[i] = hw;
        ((uint2*)g_wlo)[i] = lw;
    } else if (i < 12288) {
        int j = i - 8192;
        split4(((const float4*)pw)[j], hw, lw);
        ((uint2*)g_pwhi)[j] = hw;
        ((uint2*)g_pwlo)[j] = lw;
    }
}

// ===========================================================================
// Full-K (proj) tile layout: 128 x 128 bf16, padded rows of 272B.
// Chunked (conv) tile layout: 128 x 64 bf16, padded rows of 144B.
// Both: row stride mod 128 = 16 -> consecutive rows shift 4 banks,
// ldmatrix conflict-free (round-6-proven property).
// ===========================================================================
#define RSB  272                     // full-K row stride bytes
#define TLB  (128 * RSB)             // full-K tile = 34816B
#define A_HI 0
#define A_LO (TLB)
#define B_HI (2 * TLB)
#define B_LO (3 * TLB)
#define SMT  (4 * TLB)               // proj smem = 139264B

#define CRSB  144                    // chunk row stride bytes (64 bf16 + pad)
#define CTLB  (128 * CRSB)           // chunk tile = 18432B
#define CA_HI 0
#define CA_LO (CTLB)
#define CB_HI (2 * CTLB)
#define CB_LO (3 * CTLB)
#define CSMT  (4 * CTLB)             // conv smem = 73728B

// one split-bf16 pass over K=128 (proj): acc += A(ab) * B(bb)^T
__device__ __forceinline__ void gemm_pass(uint32_t ab, uint32_t bb, int lane,
                                          int wm, int wn, float acc[4][4][4]) {
    const int arow  = wm + (lane & 15);
    const int acolb = ((lane >> 4) << 3);
    const int brow  = wn + (lane & 7) + ((lane >> 4) << 3);
    const int bcolb = (((lane >> 3) & 1) << 3);
#pragma unroll
    for (int ks = 0; ks < 8; ks++) {
        uint32_t a[4][4], b[2][4];
        int kc = ks * 16;
#pragma unroll
        for (int mt = 0; mt < 4; mt++)
            LDMX4(a[mt], ab + (uint32_t)(arow + mt * 16) * RSB
                           + (uint32_t)(kc + acolb) * 2);
#pragma unroll
        for (int np = 0; np < 2; np++)
            LDMX4(b[np], bb + (uint32_t)(brow + np * 16) * RSB
                           + (uint32_t)(kc + bcolb) * 2);
#pragma unroll
        for (int mt = 0; mt < 4; mt++)
#pragma unroll
            for (int nt = 0; nt < 4; nt++)
                mma16816(acc[mt][nt], a[mt],
                         b[nt >> 1][(nt & 1) * 2], b[nt >> 1][(nt & 1) * 2 + 1]);
    }
}

// one split-bf16 pass over a K=64 chunk (conv)
__device__ __forceinline__ void gemm_pass64(uint32_t ab, uint32_t bb, int lane,
                                            int wm, int wn, float acc[4][4][4]) {
    const int arow  = wm + (lane & 15);
    const int acolb = ((lane >> 4) << 3);
    const int brow  = wn + (lane & 7) + ((lane >> 4) << 3);
    const int bcolb = (((lane >> 3) & 1) << 3);
#pragma unroll
    for (int ks = 0; ks < 4; ks++) {
        uint32_t a[4][4], b[2][4];
        int kc = ks * 16;
#pragma unroll
        for (int mt = 0; mt < 4; mt++)
            LDMX4(a[mt], ab + (uint32_t)(arow + mt * 16) * CRSB
                           + (uint32_t)(kc + acolb) * 2);
#pragma unroll
        for (int np = 0; np < 2; np++)
            LDMX4(b[np], bb + (uint32_t)(brow + np * 16) * CRSB
                           + (uint32_t)(kc + bcolb) * 2);
#pragma unroll
        for (int mt = 0; mt < 4; mt++)
#pragma unroll
            for (int nt = 0; nt < 4; nt++)
                mma16816(acc[mt][nt], a[mt],
                         b[nt >> 1][(nt & 1) * 2], b[nt >> 1][(nt & 1) * 2 + 1]);
    }
}

// ---------------------------------------------------------------------------
// conv 1x1: g_kv[n][o][p] = sum_c W[o][c] * X[n][p][c]
// grid (313 p-tiles, 2 o-blocks of 128, 4 n), 256 threads (8 warps: 2m x 4n).
// K in two 64-chunks -> 73.7KB smem -> 2+ blocks/SM (inter-block overlap).
// Split-commit inside each chunk: pass HI x HI overlaps LO tile loads.
// ---------------------------------------------------------------------------
__global__ void __launch_bounds__(256) conv_hmma_kernel() {
    extern __shared__ char sm[];
    uint32_t sb = smem_u32(sm);
    const int tid = threadIdx.x, wid = tid >> 5, lane = tid & 31;
    const int p0 = blockIdx.x * 128;
    const int o0 = blockIdx.y * 128;
    const int n  = blockIdx.z;
    const size_t xoff = (size_t)n * HWSZ * CD;

    const int wm = (wid & 1) * 64, wn = (wid >> 1) * 32;
    float acc[4][4][4];
#pragma unroll
    for (int i = 0; i < 4; i++)
#pragma unroll
        for (int j = 0; j < 4; j++)
#pragma unroll
            for (int k = 0; k < 4; k++) acc[i][j][k] = 0.f;

#pragma unroll
    for (int kc = 0; kc < 128; kc += 64) {
        // group 1: A_HI + B_HI (1024 segs each; 4 iters of 256 threads)
#pragma unroll
        for (int i = 0; i < 4; i++) {
            int idx = tid + i * 256;
            int c16 = idx & 7, row = idx >> 3;
            CPA16(sb + CA_HI + (uint32_t)row * CRSB + (uint32_t)c16 * 16,
                  g_whi + (size_t)(o0 + row) * CD + kc + c16 * 8);
        }
#pragma unroll
        for (int i = 0; i < 4; i++) {
            int idx = tid + i * 256;
            int c16 = idx & 7, row = idx >> 3;
            int p = p0 + row;
            int sz = (p < HWSZ) ? 16 : 0;
            int pc = (p < HWSZ) ? p : 0;
            CPA16Z(sb + CB_HI + (uint32_t)row * CRSB + (uint32_t)c16 * 16,
                   g_xhi + xoff + (size_t)pc * CD + kc + c16 * 8, sz);
        }
        CPA_COMMIT();
        // group 2: A_LO + B_LO
#pragma unroll
        for (int i = 0; i < 4; i++) {
            int idx = tid + i * 256;
            int c16 = idx & 7, row = idx >> 3;
            CPA16(sb + CA_LO + (uint32_t)row * CRSB + (uint32_t)c16 * 16,
                  g_wlo + (size_t)(o0 + row) * CD + kc + c16 * 8);
        }
#pragma unroll
        for (int i = 0; i < 4; i++) {
            int idx = tid + i * 256;
            int c16 = idx & 7, row = idx >> 3;
            int p = p0 + row;
            int sz = (p < HWSZ) ? 16 : 0;
            int pc = (p < HWSZ) ? p : 0;
            CPA16Z(sb + CB_LO + (uint32_t)row * CRSB + (uint32_t)c16 * 16,
                   g_xlo + xoff + (size_t)pc * CD + kc + c16 * 8, sz);
        }
        CPA_COMMIT();

        CPA_WAIT1();
        __syncthreads();
        gemm_pass64(sb + CA_HI, sb + CB_HI, lane, wm, wn, acc);  // overlaps LO
        CPA_WAIT0();
        __syncthreads();
        gemm_pass64(sb + CA_LO, sb + CB_HI, lane, wm, wn, acc);
        gemm_pass64(sb + CA_HI, sb + CB_LO, lane, wm, wn, acc);
        __syncthreads();   // all reads done before next chunk overwrites
    }

    const int g = lane >> 2, tg = lane & 3;
    float* O = g_kv + (size_t)n * 256 * HWSZ;
#pragma unroll
    for (int mt = 0; mt < 4; mt++) {
        int rr = o0 + wm + mt * 16 + g;
#pragma unroll
        for (int nt = 0; nt < 4; nt++) {
            int pp = p0 + wn + nt * 8 + tg * 2;
            if (pp < HWSZ) {
                *(float2*)&O[(size_t)rr * HWSZ + pp] =
                    make_float2(acc[mt][nt][0], acc[mt][nt][1]);
                *(float2*)&O[(size_t)(rr + 8) * HWSZ + pp] =
                    make_float2(acc[mt][nt][2], acc[mt][nt][3]);
            }
        }
    }
}

// ---------------------------------------------------------------------------
// projection: out[p][co] = sum_c q2[p][c] * Wp[co][c] + bias[co]
// grid (625 p-tiles of 128 over 80000), 256 threads. Split-commit (round 13).
// ---------------------------------------------------------------------------
__global__ void __launch_bounds__(256, 1)
proj_hmma_kernel(const float* __restrict__ bias, float* __restrict__ out) {
    extern __shared__ char sm[];
    uint32_t sb = smem_u32(sm);
    const int tid = threadIdx.x, wid = tid >> 5, lane = tid & 31;
    const int p0 = blockIdx.x * 128;

    // group 1: A_HI (q2hi) + B_HI (pwhi)
#pragma unroll
    for (int i = 0; i < 8; i++) {
        int idx = tid + i * 256;
        int c16 = idx & 15, row = idx >> 4;
        CPA16(sb + A_HI + (uint32_t)row * RSB + (uint32_t)c16 * 16,
              g_q2hi + (size_t)(p0 + row) * CD + c16 * 8);
    }
#pragma unroll
    for (int i = 0; i < 8; i++) {
        int idx = tid + i * 256;
        int c16 = idx & 15, row = idx >> 4;
        CPA16(sb + B_HI + (uint32_t)row * RSB + (uint32_t)c16 * 16,
              g_pwhi + (size_t)row * CD + c16 * 8);
    }
    CPA_COMMIT();
    // group 2: A_LO + B_LO
#pragma unroll
    for (int i = 0; i < 8; i++) {
        int idx = tid + i * 256;
        int c16 = idx & 15, row = idx >> 4;
        CPA16(sb + A_LO + (uint32_t)row * RSB + (uint32_t)c16 * 16,
              g_q2lo + (size_t)(p0 + row) * CD + c16 * 8);
    }
#pragma unroll
    for (int i = 0; i < 8; i++) {
        int idx = tid + i * 256;
        int c16 = idx & 15, row = idx >> 4;
        CPA16(sb + B_LO + (uint32_t)row * RSB + (uint32_t)c16 * 16,
              g_pwlo + (size_t)row * CD + c16 * 8);
    }
    CPA_COMMIT();

    const int wm = (wid & 1) * 64, wn = (wid >> 1) * 32;
    float acc[4][4][4];
#pragma unroll
    for (int i = 0; i < 4; i++)
#pragma unroll
        for (int j = 0; j < 4; j++)
#pragma unroll
            for (int k = 0; k < 4; k++) acc[i][j][k] = 0.f;

    CPA_WAIT1();
    __syncthreads();
    gemm_pass(sb + A_HI, sb + B_HI, lane, wm, wn, acc);
    CPA_WAIT0();
    __syncthreads();
    gemm_pass(sb + A_LO, sb + B_HI, lane, wm, wn, acc);
    gemm_pass(sb + A_HI, sb + B_LO, lane, wm, wn, acc);

    const int g = lane >> 2, tg = lane & 3;
#pragma unroll
    for (int mt = 0; mt < 4; mt++) {
        int p = p0 + wm + mt * 16 + g;
#pragma unroll
        for (int nt = 0; nt < 4; nt++) {
            int co = wn + nt * 8 + tg * 2;
            float b0 = bias[co], b1 = bias[co + 1];
            *(float2*)&out[(size_t)p * CD + co] =
                make_float2(acc[mt][nt][0] + b0, acc[mt][nt][1] + b1);
            *(float2*)&out[(size_t)(p + 8) * CD + co] =
                make_float2(acc[mt][nt][2] + b0, acc[mt][nt][3] + b1);
        }
    }
}

// ---------------------------------------------------------------------------
// Dilate attention, 4-way channel-packed (round-12/14 proven version).
// Stream identities: step offsets +144/+288/+432 leave (L, mask, di, dj)
// unchanged, shifting tab index by +225/+450/+675; tab[M+225k] ==
// { tab[M].x + k*640000, tab[M].y }. One tab read + one mask feeds 4 gathers.
// Thread = (pos, 64-channel slab). Block 128 thr = 64 pos x 2 slabs.
// head 1 writes its output directly as split-bf16 for the projection GEMM.
// ---------------------------------------------------------------------------
__global__ void __launch_bounds__(128, 4) attn_kernel(const float* __restrict__ qext,
                                                      int head, int dil, int stage) {
    __shared__ int2  tab[1800];
    __shared__ float st[64 * 129];
    const int tid = threadIdx.x;

    for (int m = tid; m < 1800; m += 128) {
        int c200 = m / 9;
        int kk = m - c200 * 9;
        int i = kk / 3;
        int j = kk - i * 3;
        int di = (i - 1) * dil;
        int dj = (j - 1) * dil;
        tab[m] = make_int2(c200 * 25600 + di * 128 + dj, (di << 16) | (dj & 0xFFFF));
    }
    __syncthreads();

    const float* qin = stage ? g_tmp : qext;

    const int b    = blockIdx.y;
    const int pl   = tid & 63;
    const int nh2  = tid >> 6;          // 64-channel slab: 0 or 1
    const int pos0 = blockIdx.x * 64;
    const int pos  = pos0 + pl;         // always < 40000 (625*64 == 40000)
    const int cb   = nh2 * 64;          // slab channel base

    const float* Qf = qin + (size_t)b * HWSZ * CD;
    const float* Kb = g_kv + ((size_t)(2 * b) * 256 + head * 128) * HWSZ;
    const float* Vb = g_kv + ((size_t)(2 * b + 1) * 256 + head * 128) * HWSZ;

    const int G0 = nh2 * 576 * 40000 + pos;
    const int m0 = G0 / 25600;
    const int l0 = G0 - m0 * 25600;

    // ---- pass 1: scores for both softmax groups in the slab ----
    float sc0[9], sc1[9];
#pragma unroll
    for (int k = 0; k < 9; k++) { sc0[k] = 0.f; sc1[k] = 0.f; }

    int M = m0, L = l0;
#pragma unroll 1
    for (int hd = 0; hd < 16; hd++) {
        float q0 = Qf[(size_t)(cb + hd) * HWSZ + pos];
        float q1 = Qf[(size_t)(cb + hd + 16) * HWSZ + pos];
        float q2 = Qf[(size_t)(cb + hd + 32) * HWSZ + pos];
        float q3 = Qf[(size_t)(cb + hd + 48) * HWSZ + pos];
#pragma unroll
        for (int kk = 0; kk < 9; kk++) {
            int2 t = tab[M];
            int lw = L >> 7, lc = L & 127;
            int di = t.y >> 16;
            int dj = (int)(short)(t.y & 0xFFFF);
            bool ok = ((unsigned)(lw + di) < 200u) && ((unsigned)(lc + dj) < 128u);
            int a = t.x + L;
            float k0 = ok ? __ldg(&Kb[a])           : 0.f;
            float k1 = ok ? __ldg(&Kb[a + 640000])  : 0.f;
            float k2 = ok ? __ldg(&Kb[a + 1280000]) : 0.f;
            float k3 = ok ? __ldg(&Kb[a + 1920000]) : 0.f;
            sc0[kk] = fmaf(q0, k0, sc0[kk]);
            sc0[kk] = fmaf(q1, k1, sc0[kk]);
            sc1[kk] = fmaf(q2, k2, sc1[kk]);
            sc1[kk] = fmaf(q3, k3, sc1[kk]);
            M += 1; L += 14400;
            if (L >= 25600) { L -= 25600; M += 1; }
        }
    }

    // ---- softmax over 9, per group ----
    const float SCALE = 0.17677669529663687f;   // 32^-0.5
    {
        float mx0 = -1e30f, mx1 = -1e30f;
#pragma unroll
        for (int k = 0; k < 9; k++) {
            sc0[k] *= SCALE; mx0 = fmaxf(mx0, sc0[k]);
            sc1[k] *= SCALE; mx1 = fmaxf(mx1, sc1[k]);
        }
        float s0 = 0.f, s1 = 0.f;
#pragma unroll
        for (int k = 0; k < 9; k++) {
            sc0[k] = __expf(sc0[k] - mx0); s0 += sc0[k];
            sc1[k] = __expf(sc1[k] - mx1); s1 += sc1[k];
        }
        float i0 = 1.0f / s0, i1 = 1.0f / s1;
#pragma unroll
        for (int k = 0; k < 9; k++) { sc0[k] *= i0; sc1[k] *= i1; }
    }

    // ---- pass 2: outputs ----
    M = m0; L = l0;
#pragma unroll 1
    for (int hd = 0; hd < 16; hd++) {
        float o0 = 0.f, o1 = 0.f, o2 = 0.f, o3 = 0.f;
#pragma unroll
        for (int kk = 0; kk < 9; kk++) {
            int2 t = tab[M];
            int lw = L >> 7, lc = L & 127;
            int di = t.y >> 16;
            int dj = (int)(short)(t.y & 0xFFFF);
            bool ok = ((unsigned)(lw + di) < 200u) && ((unsigned)(lc + dj) < 128u);
            int a = t.x + L;
            float v0 = ok ? __ldg(&Vb[a])           : 0.f;
            float v1 = ok ? __ldg(&Vb[a + 640000])  : 0.f;
            float v2 = ok ? __ldg(&Vb[a + 1280000]) : 0.f;
            float v3 = ok ? __ldg(&Vb[a + 1920000]) : 0.f;
            o0 = fmaf(sc0[kk], v0, o0);
            o1 = fmaf(sc0[kk], v1, o1);
            o2 = fmaf(sc1[kk], v2, o2);
            o3 = fmaf(sc1[kk], v3, o3);
            M += 1; L += 14400;
            if (L >= 25600) { L -= 25600; M += 1; }
        }
        st[pl * 129 + cb + hd]      = o0;
        st[pl * 129 + cb + hd + 16] = o1;
        st[pl * 129 + cb + hd + 32] = o2;
        st[pl * 129 + cb + hd + 48] = o3;
    }
    __syncthreads();

    // coalesced channels-last writeback: 64 pos x 128 ch contiguous
    const size_t obase = (size_t)b * HWSZ * CD + (size_t)pos0 * CD;
    if (stage) {
        __nv_bfloat16* Hh = g_q2hi + obase;
        __nv_bfloat16* Hl = g_q2lo + obase;
#pragma unroll
        for (int it = 0; it < 64; it++) {
            int f = tid + it * 128;
            int p = f >> 7, c = f & 127;
            float v = st[p * 129 + c];
            __nv_bfloat16 h = __float2bfloat16(v);
            Hh[f] = h;
            Hl[f] = __float2bfloat16(v - __bfloat162float(h));
        }
    } else {
        float* Ob = g_tmp + obase;
#pragma unroll
        for (int it = 0; it < 64; it++) {
            int f = tid + it * 128;
            int p = f >> 7, c = f & 127;
            Ob[f] = st[p * 129 + c];
        }
    }
}

extern "C" void kernel_launch(void* const* d_in, const int* in_sizes, int n_in,
                              void* d_out, int out_size) {
    const float* q   = (const float*)d_in[0];
    const float* x   = (const float*)d_in[1];
    const float* kvw = (const float*)d_in[2];
    const float* pw  = (const float*)d_in[3];
    const float* pb  = (const float*)d_in[4];
    float* out = (float*)d_out;

    cudaFuncSetAttribute(conv_hmma_kernel, cudaFuncAttributeMaxDynamicSharedMemorySize, CSMT);
    cudaFuncSetAttribute(proj_hmma_kernel, cudaFuncAttributeMaxDynamicSharedMemorySize, SMT);

    cvt_x_kernel<<<20000, 256>>>(x);
    cvt_w_kernel<<<48, 256>>>(kvw, pw);

    conv_hmma_kernel<<<dim3(313, 2, 4), 256, CSMT>>>();
    attn_kernel<<<dim3(625, 2), 128>>>(q, /*head=*/0, /*dil=*/1, /*stage=*/0);
    attn_kernel<<<dim3(625, 2), 128>>>(q, /*head=*/1, /*dil=*/2, /*stage=*/1);
    proj_hmma_kernel<<<625, 256, SMT>>>(pb, out);
}

// round 16
// speedup vs baseline: 1.2630x; 1.1164x over previous
#include <cuda_runtime.h>
#include <cuda_bf16.h>
#include <cstdint>
#include <cstddef>

#define HWSZ 40000
#define CD   128

// ---- scratch (static device globals; no runtime allocation) ----
// NOTE: only referenced from device code (host-side kernel args of __device__
// symbols give host-shadow addresses — the round-7/8 bug).
__device__ float g_kv[4UL * 256 * 40000];        // conv output [n][o][pos] fp32
__device__ float g_tmp[2UL * 40000 * 128];       // q after head 0 (channels-last fp32)
__device__ __align__(16) __nv_bfloat16 g_xhi[4UL * 40000 * 128];   // X split-bf16
__device__ __align__(16) __nv_bfloat16 g_xlo[4UL * 40000 * 128];
__device__ __align__(16) __nv_bfloat16 g_whi[256 * 128];           // conv weight split
__device__ __align__(16) __nv_bfloat16 g_wlo[256 * 128];
__device__ __align__(16) __nv_bfloat16 g_pwhi[128 * 128];          // proj weight split
__device__ __align__(16) __nv_bfloat16 g_pwlo[128 * 128];
__device__ __align__(16) __nv_bfloat16 g_q2hi[2UL * 40000 * 128];  // q after head 1, split
__device__ __align__(16) __nv_bfloat16 g_q2lo[2UL * 40000 * 128];

// ===========================================================================
// PTX helpers
// ===========================================================================
__device__ __forceinline__ uint32_t smem_u32(const void* p) {
    uint32_t a;
    asm("{ .reg .u64 t; cvta.to.shared.u64 t, %1; cvt.u32.u64 %0, t; }"
        : "=r"(a) : "l"(p));
    return a;
}
#define LDMX4(r, addr)                                                        \
    asm volatile("ldmatrix.sync.aligned.m8n8.x4.shared.b16 {%0,%1,%2,%3}, [%4];" \
                 : "=r"((r)[0]), "=r"((r)[1]), "=r"((r)[2]), "=r"((r)[3])     \
                 : "r"(addr))
__device__ __forceinline__ void mma16816(float* d, const uint32_t* a,
                                         uint32_t b0, uint32_t b1) {
    asm volatile(
        "mma.sync.aligned.m16n8k16.row.col.f32.bf16.bf16.f32 "
        "{%0,%1,%2,%3}, {%4,%5,%6,%7}, {%8,%9}, {%0,%1,%2,%3};"
        : "+f"(d[0]), "+f"(d[1]), "+f"(d[2]), "+f"(d[3])
        : "r"(a[0]), "r"(a[1]), "r"(a[2]), "r"(a[3]), "r"(b0), "r"(b1));
}
#define CPA16(dst, src) \
    asm volatile("cp.async.cg.shared.global [%0], [%1], 16;" :: "r"(dst), "l"(src) : "memory")
#define CPA16Z(dst, src, sz) \
    asm volatile("cp.async.cg.shared.global [%0], [%1], 16, %2;" :: "r"(dst), "l"(src), "r"(sz) : "memory")
#define CPA_COMMIT() asm volatile("cp.async.commit_group;" ::: "memory")
#define CPA_WAIT1()  asm volatile("cp.async.wait_group 1;" ::: "memory")
#define CPA_WAIT0()  asm volatile("cp.async.wait_group 0;" ::: "memory")

// ===========================================================================
// split-bf16 conversion pre-pass. Destinations bound IN DEVICE CODE.
// ===========================================================================
__device__ __forceinline__ void split4(float4 v, uint2& hw, uint2& lw) {
    float f[4] = {v.x, v.y, v.z, v.w};
    uint32_t h2[2] = {0, 0}, l2[2] = {0, 0};
#pragma unroll
    for (int k = 0; k < 4; k++) {
        __nv_bfloat16 h = __float2bfloat16(f[k]);
        __nv_bfloat16 l = __float2bfloat16(f[k] - __bfloat162float(h));
        h2[k >> 1] |= (uint32_t)__bfloat16_as_ushort(h) << ((k & 1) * 16);
        l2[k >> 1] |= (uint32_t)__bfloat16_as_ushort(l) << ((k & 1) * 16);
    }
    hw = make_uint2(h2[0], h2[1]);
    lw = make_uint2(l2[0], l2[1]);
}

__global__ void __launch_bounds__(256) cvt_x_kernel(const float* __restrict__ x) {
    int i = blockIdx.x * blockDim.x + threadIdx.x;   // over 5,120,000 float4
    if (i >= 5120000) return;
    uint2 hw, lw;
    split4(((const float4*)x)[i], hw, lw);
    ((uint2*)g_xhi)[i] = hw;
    ((uint2*)g_xlo)[i] = lw;
}

__global__ void __launch_bounds__(256) cvt_w_kernel(const float* __restrict__ kvw,
                                                    const float* __restrict__ pw) {
    int i = blockIdx.x * blockDim.x + threadIdx.x;   // 8192 kvw + 4096 pw float4
    uint2 hw, lw;
    if (i < 8192) {
        split4(((const float4*)kvw)[i], hw, lw);
        ((uint2*)g_whi)[i] = hw;
        ((uint2*)g_wlo)[i] = lw;
    } else if (i < 12288) {
        int j = i - 8192;
        split4(((const float4*)pw)[j], hw, lw);
        ((uint2*)g_pwhi)[j] = hw;
        ((uint2*)g_pwlo)[j] = lw;
    }
}

// ===========================================================================
// Full-K (proj) tile layout: 128 x 128 bf16, padded rows of 272B.
// Chunked (conv) tile layout: 128 x 64 bf16, padded rows of 144B.
// Both: row stride mod 128 = 16 -> consecutive rows shift 4 banks,
// ldmatrix conflict-free (round-6-proven property).
// ===========================================================================
#define RSB  272                     // full-K row stride bytes
#define TLB  (128 * RSB)             // full-K tile = 34816B
#define A_HI 0
#define A_LO (TLB)
#define B_HI (2 * TLB)
#define B_LO (3 * TLB)
#define SMT  (4 * TLB)               // proj smem = 139264B

#define CRSB  144                    // chunk row stride bytes (64 bf16 + pad)
#define CTLB  (128 * CRSB)           // chunk tile = 18432B
#define CA_HI 0
#define CA_LO (CTLB)
#define CB_HI (2 * CTLB)
#define CB_LO (3 * CTLB)
#define CSMT  (4 * CTLB)             // conv smem = 73728B

// one split-bf16 pass over K=128 (proj): acc += A(ab) * B(bb)^T
__device__ __forceinline__ void gemm_pass(uint32_t ab, uint32_t bb, int lane,
                                          int wm, int wn, float acc[4][4][4]) {
    const int arow  = wm + (lane & 15);
    const int acolb = ((lane >> 4) << 3);
    const int brow  = wn + (lane & 7) + ((lane >> 4) << 3);
    const int bcolb = (((lane >> 3) & 1) << 3);
#pragma unroll
    for (int ks = 0; ks < 8; ks++) {
        uint32_t a[4][4], b[2][4];
        int kc = ks * 16;
#pragma unroll
        for (int mt = 0; mt < 4; mt++)
            LDMX4(a[mt], ab + (uint32_t)(arow + mt * 16) * RSB
                           + (uint32_t)(kc + acolb) * 2);
#pragma unroll
        for (int np = 0; np < 2; np++)
            LDMX4(b[np], bb + (uint32_t)(brow + np * 16) * RSB
                           + (uint32_t)(kc + bcolb) * 2);
#pragma unroll
        for (int mt = 0; mt < 4; mt++)
#pragma unroll
            for (int nt = 0; nt < 4; nt++)
                mma16816(acc[mt][nt], a[mt],
                         b[nt >> 1][(nt & 1) * 2], b[nt >> 1][(nt & 1) * 2 + 1]);
    }
}

// one split-bf16 pass over a K=64 chunk (conv)
__device__ __forceinline__ void gemm_pass64(uint32_t ab, uint32_t bb, int lane,
                                            int wm, int wn, float acc[4][4][4]) {
    const int arow  = wm + (lane & 15);
    const int acolb = ((lane >> 4) << 3);
    const int brow  = wn + (lane & 7) + ((lane >> 4) << 3);
    const int bcolb = (((lane >> 3) & 1) << 3);
#pragma unroll
    for (int ks = 0; ks < 4; ks++) {
        uint32_t a[4][4], b[2][4];
        int kc = ks * 16;
#pragma unroll
        for (int mt = 0; mt < 4; mt++)
            LDMX4(a[mt], ab + (uint32_t)(arow + mt * 16) * CRSB
                           + (uint32_t)(kc + acolb) * 2);
#pragma unroll
        for (int np = 0; np < 2; np++)
            LDMX4(b[np], bb + (uint32_t)(brow + np * 16) * CRSB
                           + (uint32_t)(kc + bcolb) * 2);
#pragma unroll
        for (int mt = 0; mt < 4; mt++)
#pragma unroll
            for (int nt = 0; nt < 4; nt++)
                mma16816(acc[mt][nt], a[mt],
                         b[nt >> 1][(nt & 1) * 2], b[nt >> 1][(nt & 1) * 2 + 1]);
    }
}

// ---------------------------------------------------------------------------
// conv 1x1: g_kv[n][o][p] = sum_c W[o][c] * X[n][p][c]
// grid (313 p-tiles, 2 o-blocks of 128, 4 n), 256 threads (8 warps: 2m x 4n).
// K in two 64-chunks -> 73.7KB smem -> 2+ blocks/SM (inter-block overlap).
// Split-commit inside each chunk: pass HI x HI overlaps LO tile loads.
// ---------------------------------------------------------------------------
__global__ void __launch_bounds__(256) conv_hmma_kernel() {
    extern __shared__ char sm[];
    uint32_t sb = smem_u32(sm);
    const int tid = threadIdx.x, wid = tid >> 5, lane = tid & 31;
    const int p0 = blockIdx.x * 128;
    const int o0 = blockIdx.y * 128;
    const int n  = blockIdx.z;
    const size_t xoff = (size_t)n * HWSZ * CD;

    const int wm = (wid & 1) * 64, wn = (wid >> 1) * 32;
    float acc[4][4][4];
#pragma unroll
    for (int i = 0; i < 4; i++)
#pragma unroll
        for (int j = 0; j < 4; j++)
#pragma unroll
            for (int k = 0; k < 4; k++) acc[i][j][k] = 0.f;

#pragma unroll
    for (int kc = 0; kc < 128; kc += 64) {
        // group 1: A_HI + B_HI (1024 segs each; 4 iters of 256 threads)
#pragma unroll
        for (int i = 0; i < 4; i++) {
            int idx = tid + i * 256;
            int c16 = idx & 7, row = idx >> 3;
            CPA16(sb + CA_HI + (uint32_t)row * CRSB + (uint32_t)c16 * 16,
                  g_whi + (size_t)(o0 + row) * CD + kc + c16 * 8);
        }
#pragma unroll
        for (int i = 0; i < 4; i++) {
            int idx = tid + i * 256;
            int c16 = idx & 7, row = idx >> 3;
            int p = p0 + row;
            int sz = (p < HWSZ) ? 16 : 0;
            int pc = (p < HWSZ) ? p : 0;
            CPA16Z(sb + CB_HI + (uint32_t)row * CRSB + (uint32_t)c16 * 16,
                   g_xhi + xoff + (size_t)pc * CD + kc + c16 * 8, sz);
        }
        CPA_COMMIT();
        // group 2: A_LO + B_LO
#pragma unroll
        for (int i = 0; i < 4; i++) {
            int idx = tid + i * 256;
            int c16 = idx & 7, row = idx >> 3;
            CPA16(sb + CA_LO + (uint32_t)row * CRSB + (uint32_t)c16 * 16,
                  g_wlo + (size_t)(o0 + row) * CD + kc + c16 * 8);
        }
#pragma unroll
        for (int i = 0; i < 4; i++) {
            int idx = tid + i * 256;
            int c16 = idx & 7, row = idx >> 3;
            int p = p0 + row;
            int sz = (p < HWSZ) ? 16 : 0;
            int pc = (p < HWSZ) ? p : 0;
            CPA16Z(sb + CB_LO + (uint32_t)row * CRSB + (uint32_t)c16 * 16,
                   g_xlo + xoff + (size_t)pc * CD + kc + c16 * 8, sz);
        }
        CPA_COMMIT();

        CPA_WAIT1();
        __syncthreads();
        gemm_pass64(sb + CA_HI, sb + CB_HI, lane, wm, wn, acc);  // overlaps LO
        CPA_WAIT0();
        __syncthreads();
        gemm_pass64(sb + CA_LO, sb + CB_HI, lane, wm, wn, acc);
        gemm_pass64(sb + CA_HI, sb + CB_LO, lane, wm, wn, acc);
        __syncthreads();   // all reads done before next chunk overwrites
    }

    const int g = lane >> 2, tg = lane & 3;
    float* O = g_kv + (size_t)n * 256 * HWSZ;
#pragma unroll
    for (int mt = 0; mt < 4; mt++) {
        int rr = o0 + wm + mt * 16 + g;
#pragma unroll
        for (int nt = 0; nt < 4; nt++) {
            int pp = p0 + wn + nt * 8 + tg * 2;
            if (pp < HWSZ) {
                *(float2*)&O[(size_t)rr * HWSZ + pp] =
                    make_float2(acc[mt][nt][0], acc[mt][nt][1]);
                *(float2*)&O[(size_t)(rr + 8) * HWSZ + pp] =
                    make_float2(acc[mt][nt][2], acc[mt][nt][3]);
            }
        }
    }
}

// ---------------------------------------------------------------------------
// projection: out[p][co] = sum_c q2[p][c] * Wp[co][c] + bias[co]
// grid (625 p-tiles of 128 over 80000), 256 threads. Split-commit (round 13).
// ---------------------------------------------------------------------------
__global__ void __launch_bounds__(256, 1)
proj_hmma_kernel(const float* __restrict__ bias, float* __restrict__ out) {
    extern __shared__ char sm[];
    uint32_t sb = smem_u32(sm);
    const int tid = threadIdx.x, wid = tid >> 5, lane = tid & 31;
    const int p0 = blockIdx.x * 128;

    // group 1: A_HI (q2hi) + B_HI (pwhi)
#pragma unroll
    for (int i = 0; i < 8; i++) {
        int idx = tid + i * 256;
        int c16 = idx & 15, row = idx >> 4;
        CPA16(sb + A_HI + (uint32_t)row * RSB + (uint32_t)c16 * 16,
              g_q2hi + (size_t)(p0 + row) * CD + c16 * 8);
    }
#pragma unroll
    for (int i = 0; i < 8; i++) {
        int idx = tid + i * 256;
        int c16 = idx & 15, row = idx >> 4;
        CPA16(sb + B_HI + (uint32_t)row * RSB + (uint32_t)c16 * 16,
              g_pwhi + (size_t)row * CD + c16 * 8);
    }
    CPA_COMMIT();
    // group 2: A_LO + B_LO
#pragma unroll
    for (int i = 0; i < 8; i++) {
        int idx = tid + i * 256;
        int c16 = idx & 15, row = idx >> 4;
        CPA16(sb + A_LO + (uint32_t)row * RSB + (uint32_t)c16 * 16,
              g_q2lo + (size_t)(p0 + row) * CD + c16 * 8);
    }
#pragma unroll
    for (int i = 0; i < 8; i++) {
        int idx = tid + i * 256;
        int c16 = idx & 15, row = idx >> 4;
        CPA16(sb + B_LO + (uint32_t)row * RSB + (uint32_t)c16 * 16,
              g_pwlo + (size_t)row * CD + c16 * 8);
    }
    CPA_COMMIT();

    const int wm = (wid & 1) * 64, wn = (wid >> 1) * 32;
    float acc[4][4][4];
#pragma unroll
    for (int i = 0; i < 4; i++)
#pragma unroll
        for (int j = 0; j < 4; j++)
#pragma unroll
            for (int k = 0; k < 4; k++) acc[i][j][k] = 0.f;

    CPA_WAIT1();
    __syncthreads();
    gemm_pass(sb + A_HI, sb + B_HI, lane, wm, wn, acc);
    CPA_WAIT0();
    __syncthreads();
    gemm_pass(sb + A_LO, sb + B_HI, lane, wm, wn, acc);
    gemm_pass(sb + A_HI, sb + B_LO, lane, wm, wn, acc);

    const int g = lane >> 2, tg = lane & 3;
#pragma unroll
    for (int mt = 0; mt < 4; mt++) {
        int p = p0 + wm + mt * 16 + g;
#pragma unroll
        for (int nt = 0; nt < 4; nt++) {
            int co = wn + nt * 8 + tg * 2;
            float b0 = bias[co], b1 = bias[co + 1];
            *(float2*)&out[(size_t)p * CD + co] =
                make_float2(acc[mt][nt][0] + b0, acc[mt][nt][1] + b1);
            *(float2*)&out[(size_t)(p + 8) * CD + co] =
                make_float2(acc[mt][nt][2] + b0, acc[mt][nt][3] + b1);
        }
    }
}

// ---------------------------------------------------------------------------
// Dilate attention, 4-way channel-packed, WINDOWED tab (36.7KB smem ->
// 5 blocks/SM = 20 warps). Each slab's M-stream only touches the window
// [900*nh2, 900*nh2 + 226]: m0 = 900*nh2 + floor(pos/25600) and the stream
// adds at most 225 (143 steps + <=82 wraps). Store per-slab windows
// tab2[s][m'] = tab_global[900*s + m']; recurrence unchanged with M local.
// One tab read + one mask feeds 4 gathers at +0/+640000/+1280000/+1920000.
// head 1 writes its output directly as split-bf16 for the projection GEMM.
// ---------------------------------------------------------------------------
#define TWIN 232   // per-slab tab window (>= 227, padded)

__global__ void __launch_bounds__(128, 5) attn_kernel(const float* __restrict__ qext,
                                                      int head, int dil, int stage) {
    __shared__ int2  tab[2 * TWIN];      // 3712B: [slab][m']
    __shared__ float st[64 * 129];       // 33024B
    const int tid = threadIdx.x;

    for (int idx = tid; idx < 2 * TWIN; idx += 128) {
        int s  = idx / TWIN;
        int mp = idx - s * TWIN;
        int m  = s * 900 + mp;           // global m < 1800 always
        int c200 = m / 9;
        int kk = m - c200 * 9;
        int i = kk / 3;
        int j = kk - i * 3;
        int di = (i - 1) * dil;
        int dj = (j - 1) * dil;
        tab[idx] = make_int2(c200 * 25600 + di * 128 + dj, (di << 16) | (dj & 0xFFFF));
    }
    __syncthreads();

    const float* qin = stage ? g_tmp : qext;

    const int b    = blockIdx.y;
    const int pl   = tid & 63;
    const int nh2  = tid >> 6;          // 64-channel slab: 0 or 1
    const int pos0 = blockIdx.x * 64;
    const int pos  = pos0 + pl;         // always < 40000 (625*64 == 40000)
    const int cb   = nh2 * 64;          // slab channel base
    const int tbase = nh2 * TWIN;       // slab tab window base

    const float* Qf = qin + (size_t)b * HWSZ * CD;
    const float* Kb = g_kv + ((size_t)(2 * b) * 256 + head * 128) * HWSZ;
    const float* Vb = g_kv + ((size_t)(2 * b + 1) * 256 + head * 128) * HWSZ;

    // slab-local (M, L): m0_local = floor(pos/25600), l0 = pos mod 25600
    const int m0 = pos / 25600;
    const int l0 = pos - m0 * 25600;

    // ---- pass 1: scores for both softmax groups in the slab ----
    float sc0[9], sc1[9];
#pragma unroll
    for (int k = 0; k < 9; k++) { sc0[k] = 0.f; sc1[k] = 0.f; }

    int M = m0, L = l0;
#pragma unroll 1
    for (int hd = 0; hd < 16; hd++) {
        float q0 = Qf[(size_t)(cb + hd) * HWSZ + pos];
        float q1 = Qf[(size_t)(cb + hd + 16) * HWSZ + pos];
        float q2 = Qf[(size_t)(cb + hd + 32) * HWSZ + pos];
        float q3 = Qf[(size_t)(cb + hd + 48) * HWSZ + pos];
#pragma unroll
        for (int kk = 0; kk < 9; kk++) {
            int2 t = tab[tbase + M];
            int lw = L >> 7, lc = L & 127;
            int di = t.y >> 16;
            int dj = (int)(short)(t.y & 0xFFFF);
            bool ok = ((unsigned)(lw + di) < 200u) && ((unsigned)(lc + dj) < 128u);
            int a = t.x + L;
            float k0 = ok ? __ldg(&Kb[a])           : 0.f;
            float k1 = ok ? __ldg(&Kb[a + 640000])  : 0.f;
            float k2 = ok ? __ldg(&Kb[a + 1280000]) : 0.f;
            float k3 = ok ? __ldg(&Kb[a + 1920000]) : 0.f;
            sc0[kk] = fmaf(q0, k0, sc0[kk]);
            sc0[kk] = fmaf(q1, k1, sc0[kk]);
            sc1[kk] = fmaf(q2, k2, sc1[kk]);
            sc1[kk] = fmaf(q3, k3, sc1[kk]);
            M += 1; L += 14400;
            if (L >= 25600) { L -= 25600; M += 1; }
        }
    }

    // ---- softmax over 9, per group ----
    const float SCALE = 0.17677669529663687f;   // 32^-0.5
    {
        float mx0 = -1e30f, mx1 = -1e30f;
#pragma unroll
        for (int k = 0; k < 9; k++) {
            sc0[k] *= SCALE; mx0 = fmaxf(mx0, sc0[k]);
            sc1[k] *= SCALE; mx1 = fmaxf(mx1, sc1[k]);
        }
        float s0 = 0.f, s1 = 0.f;
#pragma unroll
        for (int k = 0; k < 9; k++) {
            sc0[k] = __expf(sc0[k] - mx0); s0 += sc0[k];
            sc1[k] = __expf(sc1[k] - mx1); s1 += sc1[k];
        }
        float i0 = 1.0f / s0, i1 = 1.0f / s1;
#pragma unroll
        for (int k = 0; k < 9; k++) { sc0[k] *= i0; sc1[k] *= i1; }
    }

    // ---- pass 2: outputs ----
    M = m0; L = l0;
#pragma unroll 1
    for (int hd = 0; hd < 16; hd++) {
        float o0 = 0.f, o1 = 0.f, o2 = 0.f, o3 = 0.f;
#pragma unroll
        for (int kk = 0; kk < 9; kk++) {
            int2 t = tab[tbase + M];
            int lw = L >> 7, lc = L & 127;
            int di = t.y >> 16;
            int dj = (int)(short)(t.y & 0xFFFF);
            bool ok = ((unsigned)(lw + di) < 200u) && ((unsigned)(lc + dj) < 128u);
            int a = t.x + L;
            float v0 = ok ? __ldg(&Vb[a])           : 0.f;
            float v1 = ok ? __ldg(&Vb[a + 640000])  : 0.f;
            float v2 = ok ? __ldg(&Vb[a + 1280000]) : 0.f;
            float v3 = ok ? __ldg(&Vb[a + 1920000]) : 0.f;
            o0 = fmaf(sc0[kk], v0, o0);
            o1 = fmaf(sc0[kk], v1, o1);
            o2 = fmaf(sc1[kk], v2, o2);
            o3 = fmaf(sc1[kk], v3, o3);
            M += 1; L += 14400;
            if (L >= 25600) { L -= 25600; M += 1; }
        }
        st[pl * 129 + cb + hd]      = o0;
        st[pl * 129 + cb + hd + 16] = o1;
        st[pl * 129 + cb + hd + 32] = o2;
        st[pl * 129 + cb + hd + 48] = o3;
    }
    __syncthreads();

    // coalesced channels-last writeback: 64 pos x 128 ch contiguous
    const size_t obase = (size_t)b * HWSZ * CD + (size_t)pos0 * CD;
    if (stage) {
        __nv_bfloat16* Hh = g_q2hi + obase;
        __nv_bfloat16* Hl = g_q2lo + obase;
#pragma unroll
        for (int it = 0; it < 64; it++) {
            int f = tid + it * 128;
            int p = f >> 7, c = f & 127;
            float v = st[p * 129 + c];
            __nv_bfloat16 h = __float2bfloat16(v);
            Hh[f] = h;
            Hl[f] = __float2bfloat16(v - __bfloat162float(h));
        }
    } else {
        float* Ob = g_tmp + obase;
#pragma unroll
        for (int it = 0; it < 64; it++) {
            int f = tid + it * 128;
            int p = f >> 7, c = f & 127;
            Ob[f] = st[p * 129 + c];
        }
    }
}

extern "C" void kernel_launch(void* const* d_in, const int* in_sizes, int n_in,
                              void* d_out, int out_size) {
    const float* q   = (const float*)d_in[0];
    const float* x   = (const float*)d_in[1];
    const float* kvw = (const float*)d_in[2];
    const float* pw  = (const float*)d_in[3];
    const float* pb  = (const float*)d_in[4];
    float* out = (float*)d_out;

    cudaFuncSetAttribute(conv_hmma_kernel, cudaFuncAttributeMaxDynamicSharedMemorySize, CSMT);
    cudaFuncSetAttribute(proj_hmma_kernel, cudaFuncAttributeMaxDynamicSharedMemorySize, SMT);

    cvt_x_kernel<<<20000, 256>>>(x);
    cvt_w_kernel<<<48, 256>>>(kvw, pw);

    conv_hmma_kernel<<<dim3(313, 2, 4), 256, CSMT>>>();
    attn_kernel<<<dim3(625, 2), 128>>>(q, /*head=*/0, /*dil=*/1, /*stage=*/0);
    attn_kernel<<<dim3(625, 2), 128>>>(q, /*head=*/1, /*dil=*/2, /*stage=*/1);
    proj_hmma_kernel<<<625, 256, SMT>>>(pb, out);
}